// round 14
// baseline (speedup 1.0000x reference)
#include <cuda_runtime.h>
#include <cuda_fp16.h>

#define NN 100000
#define NE 3200000

// ---- scratch (device globals; no allocation allowed) ----
__device__ __align__(128) float4 g_u[NN * 8];   // per-node dst-side layer-1 partial (+b1)
__device__ __align__(128) float4 g_v[NN * 8];   // per-node src-side layer-1 partial
__device__ float  g_agg1[NN * 2];   // encoder aggregation (HID=2)
__device__ float  g_cnt[NN];        // in-degree counts
__device__ float  g_stats[8];       // BN: col sums [0..3], col sumsq [4..7]

__device__ __forceinline__ float frelu(float x) { return fmaxf(x, 0.0f); }

// fp16 hi/lo split helpers (Markidis-style fp32 emulation on HMMA)
__device__ __forceinline__ void splith2(float x, float y, unsigned& hi, unsigned& lo) {
    __half2 h = __floats2half2_rn(x, y);
    float2 fb = __half22float2(h);
    __half2 l = __floats2half2_rn(x - fb.x, y - fb.y);
    hi = *reinterpret_cast<unsigned*>(&h);
    lo = *reinterpret_cast<unsigned*>(&l);
}

__device__ __forceinline__ unsigned h2u(__half2 h) {
    return *reinterpret_cast<unsigned*>(&h);
}

// pack two fp32 to fp16x2 with relu applied post-round (== pre-round relu)
__device__ __forceinline__ unsigned pkrelu(float x, float y) {
    __half2 z = __float2half2_rn(0.0f);
    return h2u(__hmax2(__floats2half2_rn(x, y), z));
}

__device__ __forceinline__ void mma16816(float& c0, float& c1, float& c2, float& c3,
                                         unsigned a0, unsigned a1, unsigned a2, unsigned a3,
                                         unsigned b0, unsigned b1) {
    asm volatile(
        "mma.sync.aligned.m16n8k16.row.col.f32.f16.f16.f32 "
        "{%0,%1,%2,%3}, {%4,%5,%6,%7}, {%8,%9}, {%0,%1,%2,%3};\n"
        : "+f"(c0), "+f"(c1), "+f"(c2), "+f"(c3)
        : "r"(a0), "r"(a1), "r"(a2), "r"(a3), "r"(b0), "r"(b1));
}

// ---- zero the per-replay accumulators ----
__global__ void k_zero(float* __restrict__ out) {
    int i = blockIdx.x * blockDim.x + threadIdx.x;
    const int total = 8 + NN + NN * 2 + NN * 4;
    if (i >= total) return;
    if (i < 8)               g_stats[i] = 0.0f;
    else if (i < 8 + NN)     g_cnt[i - 8] = 0.0f;
    else if (i < 8 + 3 * NN) g_agg1[i - 8 - NN] = 0.0f;
    else                     out[i - 8 - 3 * NN] = 0.0f;
}

// ---- BatchNorm statistics ----
__global__ void k_stats(const float4* __restrict__ x) {
    float s[8] = {0, 0, 0, 0, 0, 0, 0, 0};
    for (int i = blockIdx.x * blockDim.x + threadIdx.x; i < NN;
         i += gridDim.x * blockDim.x) {
        float4 v = x[i];
        s[0] += v.x; s[1] += v.y; s[2] += v.z; s[3] += v.w;
        s[4] += v.x * v.x; s[5] += v.y * v.y; s[6] += v.z * v.z; s[7] += v.w * v.w;
    }
#pragma unroll
    for (int k = 0; k < 8; k++) {
#pragma unroll
        for (int o = 16; o > 0; o >>= 1)
            s[k] += __shfl_down_sync(0xffffffffu, s[k], o);
    }
    __shared__ float sh[8][8];
    int w = threadIdx.x >> 5, l = threadIdx.x & 31;
    if (l == 0) {
#pragma unroll
        for (int k = 0; k < 8; k++) sh[w][k] = s[k];
    }
    __syncthreads();
    if (threadIdx.x < 8) {
        float t = 0.0f;
#pragma unroll
        for (int ww = 0; ww < 8; ww++) t += sh[ww][threadIdx.x];
        atomicAdd(&g_stats[threadIdx.x], t);
    }
}

// ---- per-node: BN normalize + encoder layer-1 hoist ----
__global__ void k_pre_enc(const float4* __restrict__ x,
                          const float* __restrict__ w1, const float* __restrict__ b1,
                          const float* __restrict__ bnw, const float* __restrict__ bnb) {
    __shared__ float sWd[4][32], sWs[4][32], sB[32];
    __shared__ float sm[4], sinv[4], sbw[4], sbb[4];
    int t = threadIdx.x;
    if (t < 128) {
        int c = t >> 5, j = t & 31;
        float a = w1[c * 32 + j], b = w1[(c + 4) * 32 + j];
        sWd[c][j] = a - b;
        sWs[c][j] = b;
    }
    if (t < 32) sB[t] = b1[t];
    if (t < 4) {
        float mean = g_stats[t] * (1.0f / NN);
        float var  = g_stats[4 + t] * (1.0f / NN) - mean * mean;
        sm[t] = mean;
        sinv[t] = rsqrtf(var + 1e-5f);
        sbw[t] = bnw[t];
        sbb[t] = bnb[t];
    }
    __syncthreads();
    int i = blockIdx.x * blockDim.x + t;
    if (i >= NN) return;
    float4 xv = x[i];
    float xh[4];
    xh[0] = (xv.x - sm[0]) * sinv[0] * sbw[0] + sbb[0];
    xh[1] = (xv.y - sm[1]) * sinv[1] * sbw[1] + sbb[1];
    xh[2] = (xv.z - sm[2]) * sinv[2] * sbw[2] + sbb[2];
    xh[3] = (xv.w - sm[3]) * sinv[3] * sbw[3] + sbb[3];
    float u[32], v[32];
#pragma unroll
    for (int j = 0; j < 32; j++) {
        float uu = sB[j], vv = 0.0f;
#pragma unroll
        for (int c = 0; c < 4; c++) {
            uu += xh[c] * sWd[c][j];
            vv += xh[c] * sWs[c][j];
        }
        u[j] = uu; v[j] = vv;
    }
#pragma unroll
    for (int j4 = 0; j4 < 8; j4++) {
        g_u[i * 8 + j4] = make_float4(u[4 * j4], u[4 * j4 + 1], u[4 * j4 + 2], u[4 * j4 + 3]);
        g_v[i * 8 + j4] = make_float4(v[4 * j4], v[4 * j4 + 1], v[4 * j4 + 2], v[4 * j4 + 3]);
    }
}

// ---- per-edge MLP: tensor cores; A-side fp16-hi, B2 hi+lo (2-pass) ----
// Block = 128 threads = 4 warps; warp owns a 64-edge tile; block = 256 edges.
// h tile stored as half2, row stride 20 words (80B): LDS.32 A-feeds conflict-free.
// Weights staged once per block in smem (conflict-free padded layout).
template <bool ENC>
__global__ void __launch_bounds__(128, 5) k_edge(const int* __restrict__ src,
                                                 const int* __restrict__ dst,
                                                 const float* __restrict__ w2,
                                                 const float* __restrict__ b2,
                                                 const float* __restrict__ w3,
                                                 const float* __restrict__ b3,
                                                 float* __restrict__ agg) {
    constexpr int OUT = ENC ? 2 : 4;
    constexpr int RW = 20;                   // u32 words per row (80B)
    __shared__ unsigned sHh[4][64 * RW];     // fp16-hi h tiles, 20KB
    __shared__ __align__(16) float sW2p[32 * 36];  // padded W2 (conflict-free frag build)
    __shared__ float sB2f[32];

    int t = threadIdx.x;
#pragma unroll
    for (int r = 0; r < 8; r++) {
        int idx = r * 128 + t;               // 1024 W2 entries
        sW2p[(idx >> 5) * 36 + (idx & 31)] = w2[idx];
    }
    if (t < 32) sB2f[t] = b2[t];
    __syncthreads();

    int warp = t >> 5, lane = t & 31;
    int base = blockIdx.x * 256 + warp * 64;
    unsigned* hb = sHh[warp];

    // ---- Phase 1: cooperative gather + stage h (fp16 hi, relu fused) ----
    {
        int q = lane >> 3, c = lane & 7;
#pragma unroll 8
        for (int g = 0; g < 16; g++) {
            int row = g * 4 + q;
            int e   = base + row;
            int sn  = src[e];
            int dn  = dst[e];
            float4 uu = g_u[dn * 8 + c];
            float4 vv = g_v[sn * 8 + c];
            unsigned a = pkrelu(uu.x + vv.x, uu.y + vv.y);
            unsigned b = pkrelu(uu.z + vv.z, uu.w + vv.w);
            *reinterpret_cast<uint2*>(hb + row * RW + 2 * c) = make_uint2(a, b);
        }
    }
    __syncwarp();

    int gg = lane >> 2, tt = lane & 3;

    // ---- B2 fragments (register-resident, hi/lo) from smem ----
    unsigned B2h[2][4][2], B2l[2][4][2];
#pragma unroll
    for (int kt = 0; kt < 2; kt++) {
#pragma unroll
        for (int nt = 0; nt < 4; nt++) {
            int k = kt * 16 + 2 * tt, n = nt * 8 + gg;
            splith2(sW2p[k * 36 + n],       sW2p[(k + 1) * 36 + n], B2h[kt][nt][0], B2l[kt][nt][0]);
            splith2(sW2p[(k + 8) * 36 + n], sW2p[(k + 9) * 36 + n], B2h[kt][nt][1], B2l[kt][nt][1]);
        }
    }

    // ---- B3 fragments (W3[32xOUT] zero-padded to n=8), hi/lo ----
    unsigned B3h[2][2], B3l[2][2];
#pragma unroll
    for (int p = 0; p < 2; p++) {
        int j0 = p * 16 + 2 * tt;
        float wa = (gg < OUT) ? w3[j0 * OUT + gg]       : 0.0f;
        float wb = (gg < OUT) ? w3[(j0 + 1) * OUT + gg] : 0.0f;
        float wc = (gg < OUT) ? w3[(j0 + 8) * OUT + gg] : 0.0f;
        float wd = (gg < OUT) ? w3[(j0 + 9) * OUT + gg] : 0.0f;
        splith2(wa, wb, B3h[p][0], B3l[p][0]);
        splith2(wc, wd, B3h[p][1], B3l[p][1]);
    }
    float b3c0 = (2 * tt < OUT)     ? b3[2 * tt]     : 0.0f;
    float b3c1 = (2 * tt + 1 < OUT) ? b3[2 * tt + 1] : 0.0f;

    float2 b2p[4];
#pragma unroll
    for (int nt = 0; nt < 4; nt++)
        b2p[nt] = *reinterpret_cast<const float2*>(&sB2f[nt * 8 + 2 * tt]);

    // ---- Phase 2: per-mt GEMM chain + immediate scatter ----
#pragma unroll
    for (int mt = 0; mt < 4; mt++) {
        int r0 = mt * 16 + gg;

        float acc[4][4];
#pragma unroll
        for (int nt = 0; nt < 4; nt++) {
            acc[nt][0] = b2p[nt].x; acc[nt][1] = b2p[nt].y;
            acc[nt][2] = b2p[nt].x; acc[nt][3] = b2p[nt].y;
        }

#pragma unroll
        for (int kt = 0; kt < 2; kt++) {
            int wbase = r0 * RW + kt * 8 + tt;
            unsigned Ah0 = hb[wbase];              // (r0,   cols k,k+1)
            unsigned Ah1 = hb[wbase + 8 * RW];     // (r0+8, cols k,k+1)
            unsigned Ah2 = hb[wbase + 4];          // (r0,   cols k+8,k+9)
            unsigned Ah3 = hb[wbase + 8 * RW + 4]; // (r0+8, cols k+8,k+9)
#pragma unroll
            for (int nt = 0; nt < 4; nt++) {
                mma16816(acc[nt][0], acc[nt][1], acc[nt][2], acc[nt][3],
                         Ah0, Ah1, Ah2, Ah3, B2h[kt][nt][0], B2h[kt][nt][1]);
                mma16816(acc[nt][0], acc[nt][1], acc[nt][2], acc[nt][3],
                         Ah0, Ah1, Ah2, Ah3, B2l[kt][nt][0], B2l[kt][nt][1]);
            }
        }

        // ---- layer 3: relu(C2) -> fp16-hi A fragments -> second MMA chain ----
        float o0 = b3c0, o1 = b3c1, o2 = b3c0, o3 = b3c1;
#pragma unroll
        for (int p = 0; p < 2; p++) {
            unsigned Ah[4];
            Ah[0] = pkrelu(acc[2 * p][0],     acc[2 * p][1]);
            Ah[1] = pkrelu(acc[2 * p][2],     acc[2 * p][3]);
            Ah[2] = pkrelu(acc[2 * p + 1][0], acc[2 * p + 1][1]);
            Ah[3] = pkrelu(acc[2 * p + 1][2], acc[2 * p + 1][3]);
            mma16816(o0, o1, o2, o3, Ah[0], Ah[1], Ah[2], Ah[3], B3h[p][0], B3h[p][1]);
            mma16816(o0, o1, o2, o3, Ah[0], Ah[1], Ah[2], Ah[3], B3l[p][0], B3l[p][1]);
        }

        // ---- scatter: C3 rows r0, r0+8; cols 2tt, 2tt+1 ----
        if (ENC) {
            if (tt == 0) {
                int d0 = dst[base + r0];
                atomicAdd(&g_agg1[d0 * 2 + 0], frelu(o0));
                atomicAdd(&g_agg1[d0 * 2 + 1], frelu(o1));
                atomicAdd(&g_cnt[d0], 1.0f);
                int d1 = dst[base + r0 + 8];
                atomicAdd(&g_agg1[d1 * 2 + 0], frelu(o2));
                atomicAdd(&g_agg1[d1 * 2 + 1], frelu(o3));
                atomicAdd(&g_cnt[d1], 1.0f);
            }
        } else {
            if (tt < 2) {
                int d0 = dst[base + r0];
                atomicAdd(&agg[d0 * 4 + 2 * tt + 0], o0);
                atomicAdd(&agg[d0 * 4 + 2 * tt + 1], o1);
                int d1 = dst[base + r0 + 8];
                atomicAdd(&agg[d1 * 4 + 2 * tt + 0], o2);
                atomicAdd(&agg[d1 * 4 + 2 * tt + 1], o3);
            }
        }
    }
}

// ---- finalize encoder (mean) + decoder layer-1 hoist into g_u/g_v ----
__global__ void k_fin1(const float* __restrict__ dw1, const float* __restrict__ db1) {
    __shared__ float sWd[2][32], sWs[2][32], sB[32];
    int t = threadIdx.x;
    if (t < 64) {
        int c = t >> 5, j = t & 31;
        float a = dw1[c * 32 + j], b = dw1[(c + 2) * 32 + j];
        sWd[c][j] = a - b;
        sWs[c][j] = b;
    }
    if (t < 32) sB[t] = db1[t];
    __syncthreads();
    int i = blockIdx.x * blockDim.x + t;
    if (i >= NN) return;
    float inv = 1.0f / fmaxf(g_cnt[i], 1.0f);
    float h0 = g_agg1[i * 2 + 0] * inv;
    float h1 = g_agg1[i * 2 + 1] * inv;
    float u[32], v[32];
#pragma unroll
    for (int j = 0; j < 32; j++) {
        u[j] = sB[j] + h0 * sWd[0][j] + h1 * sWd[1][j];
        v[j] = h0 * sWs[0][j] + h1 * sWs[1][j];
    }
#pragma unroll
    for (int j4 = 0; j4 < 8; j4++) {
        g_u[i * 8 + j4] = make_float4(u[4 * j4], u[4 * j4 + 1], u[4 * j4 + 2], u[4 * j4 + 3]);
        g_v[i * 8 + j4] = make_float4(v[4 * j4], v[4 * j4 + 1], v[4 * j4 + 2], v[4 * j4 + 3]);
    }
}

// ---- finalize output: divide by counts ----
__global__ void k_fin2(float* __restrict__ out) {
    int i = blockIdx.x * blockDim.x + threadIdx.x;
    if (i >= NN) return;
    float inv = 1.0f / fmaxf(g_cnt[i], 1.0f);
    float4 v = ((float4*)out)[i];
    v.x *= inv; v.y *= inv; v.z *= inv; v.w *= inv;
    ((float4*)out)[i] = v;
}

extern "C" void kernel_launch(void* const* d_in, const int* in_sizes, int n_in,
                              void* d_out, int out_size) {
    const float* x    = (const float*)d_in[0];
    const int*   ei   = (const int*)d_in[1];
    const float* bnw  = (const float*)d_in[2];
    const float* bnb  = (const float*)d_in[3];
    const float* ew1  = (const float*)d_in[4];
    const float* eb1  = (const float*)d_in[5];
    const float* ew2  = (const float*)d_in[6];
    const float* eb2  = (const float*)d_in[7];
    const float* ew3  = (const float*)d_in[8];
    const float* eb3  = (const float*)d_in[9];
    const float* dw1  = (const float*)d_in[10];
    const float* db1  = (const float*)d_in[11];
    const float* dw2  = (const float*)d_in[12];
    const float* db2  = (const float*)d_in[13];
    const float* dw3  = (const float*)d_in[14];
    const float* db3  = (const float*)d_in[15];
    float* out = (float*)d_out;

    const int* src = ei;
    const int* dst = ei + NE;

    const int zero_total = 8 + NN + NN * 2 + NN * 4;
    k_zero<<<(zero_total + 255) / 256, 256>>>(out);
    k_stats<<<400, 256>>>((const float4*)x);
    k_pre_enc<<<(NN + 255) / 256, 256>>>((const float4*)x, ew1, eb1, bnw, bnb);
    k_edge<true><<<NE / 256, 128>>>(src, dst, ew2, eb2, ew3, eb3, nullptr);
    k_fin1<<<(NN + 255) / 256, 256>>>(dw1, db1);
    k_edge<false><<<NE / 256, 128>>>(src, dst, dw2, db2, dw3, db3, out);
    k_fin2<<<(NN + 255) / 256, 256>>>(out);
}

// round 16
// speedup vs baseline: 1.5153x; 1.5153x over previous
#include <cuda_runtime.h>
#include <cuda_fp16.h>

#define NN 100000
#define NE 3200000

// ---- scratch (device globals; no allocation allowed) ----
__device__ __align__(128) float4 g_u[NN * 8];   // per-node dst-side layer-1 partial (+b1)
__device__ __align__(128) float4 g_v[NN * 8];   // per-node src-side layer-1 partial
__device__ float  g_agg1[NN * 2];   // encoder aggregation (HID=2)
__device__ float  g_cnt[NN];        // in-degree counts
__device__ float  g_stats[8];       // BN: col sums [0..3], col sumsq [4..7]

__device__ __forceinline__ float frelu(float x) { return fmaxf(x, 0.0f); }

// fp16 hi/lo split helpers (Markidis-style fp32 emulation on HMMA)
__device__ __forceinline__ void splith2(float x, float y, unsigned& hi, unsigned& lo) {
    __half2 h = __floats2half2_rn(x, y);
    float2 fb = __half22float2(h);
    __half2 l = __floats2half2_rn(x - fb.x, y - fb.y);
    hi = *reinterpret_cast<unsigned*>(&h);
    lo = *reinterpret_cast<unsigned*>(&l);
}

__device__ __forceinline__ unsigned h2u(__half2 h) {
    return *reinterpret_cast<unsigned*>(&h);
}

// pack two fp32 to fp16x2 with relu applied post-round (== pre-round relu)
__device__ __forceinline__ unsigned pkrelu(float x, float y) {
    __half2 z = __float2half2_rn(0.0f);
    return h2u(__hmax2(__floats2half2_rn(x, y), z));
}

__device__ __forceinline__ void mma16816(float& c0, float& c1, float& c2, float& c3,
                                         unsigned a0, unsigned a1, unsigned a2, unsigned a3,
                                         unsigned b0, unsigned b1) {
    asm volatile(
        "mma.sync.aligned.m16n8k16.row.col.f32.f16.f16.f32 "
        "{%0,%1,%2,%3}, {%4,%5,%6,%7}, {%8,%9}, {%0,%1,%2,%3};\n"
        : "+f"(c0), "+f"(c1), "+f"(c2), "+f"(c3)
        : "r"(a0), "r"(a1), "r"(a2), "r"(a3), "r"(b0), "r"(b1));
}

// ---- zero the per-replay accumulators ----
__global__ void k_zero(float* __restrict__ out) {
    int i = blockIdx.x * blockDim.x + threadIdx.x;
    const int total = 8 + NN + NN * 2 + NN * 4;
    if (i >= total) return;
    if (i < 8)               g_stats[i] = 0.0f;
    else if (i < 8 + NN)     g_cnt[i - 8] = 0.0f;
    else if (i < 8 + 3 * NN) g_agg1[i - 8 - NN] = 0.0f;
    else                     out[i - 8 - 3 * NN] = 0.0f;
}

// ---- BatchNorm statistics ----
__global__ void k_stats(const float4* __restrict__ x) {
    float s[8] = {0, 0, 0, 0, 0, 0, 0, 0};
    for (int i = blockIdx.x * blockDim.x + threadIdx.x; i < NN;
         i += gridDim.x * blockDim.x) {
        float4 v = x[i];
        s[0] += v.x; s[1] += v.y; s[2] += v.z; s[3] += v.w;
        s[4] += v.x * v.x; s[5] += v.y * v.y; s[6] += v.z * v.z; s[7] += v.w * v.w;
    }
#pragma unroll
    for (int k = 0; k < 8; k++) {
#pragma unroll
        for (int o = 16; o > 0; o >>= 1)
            s[k] += __shfl_down_sync(0xffffffffu, s[k], o);
    }
    __shared__ float sh[8][8];
    int w = threadIdx.x >> 5, l = threadIdx.x & 31;
    if (l == 0) {
#pragma unroll
        for (int k = 0; k < 8; k++) sh[w][k] = s[k];
    }
    __syncthreads();
    if (threadIdx.x < 8) {
        float t = 0.0f;
#pragma unroll
        for (int ww = 0; ww < 8; ww++) t += sh[ww][threadIdx.x];
        atomicAdd(&g_stats[threadIdx.x], t);
    }
}

// ---- per-node: BN normalize + encoder layer-1 hoist ----
__global__ void k_pre_enc(const float4* __restrict__ x,
                          const float* __restrict__ w1, const float* __restrict__ b1,
                          const float* __restrict__ bnw, const float* __restrict__ bnb) {
    __shared__ float sWd[4][32], sWs[4][32], sB[32];
    __shared__ float sm[4], sinv[4], sbw[4], sbb[4];
    int t = threadIdx.x;
    if (t < 128) {
        int c = t >> 5, j = t & 31;
        float a = w1[c * 32 + j], b = w1[(c + 4) * 32 + j];
        sWd[c][j] = a - b;
        sWs[c][j] = b;
    }
    if (t < 32) sB[t] = b1[t];
    if (t < 4) {
        float mean = g_stats[t] * (1.0f / NN);
        float var  = g_stats[4 + t] * (1.0f / NN) - mean * mean;
        sm[t] = mean;
        sinv[t] = rsqrtf(var + 1e-5f);
        sbw[t] = bnw[t];
        sbb[t] = bnb[t];
    }
    __syncthreads();
    int i = blockIdx.x * blockDim.x + t;
    if (i >= NN) return;
    float4 xv = x[i];
    float xh[4];
    xh[0] = (xv.x - sm[0]) * sinv[0] * sbw[0] + sbb[0];
    xh[1] = (xv.y - sm[1]) * sinv[1] * sbw[1] + sbb[1];
    xh[2] = (xv.z - sm[2]) * sinv[2] * sbw[2] + sbb[2];
    xh[3] = (xv.w - sm[3]) * sinv[3] * sbw[3] + sbb[3];
    float u[32], v[32];
#pragma unroll
    for (int j = 0; j < 32; j++) {
        float uu = sB[j], vv = 0.0f;
#pragma unroll
        for (int c = 0; c < 4; c++) {
            uu += xh[c] * sWd[c][j];
            vv += xh[c] * sWs[c][j];
        }
        u[j] = uu; v[j] = vv;
    }
#pragma unroll
    for (int j4 = 0; j4 < 8; j4++) {
        g_u[i * 8 + j4] = make_float4(u[4 * j4], u[4 * j4 + 1], u[4 * j4 + 2], u[4 * j4 + 3]);
        g_v[i * 8 + j4] = make_float4(v[4 * j4], v[4 * j4 + 1], v[4 * j4 + 2], v[4 * j4 + 3]);
    }
}

// ---- per-edge MLP: tensor cores; A-side fp16-hi, B2 hi+lo (2-pass) ----
// Block = 128 threads = 4 warps; warp owns a 64-edge tile; block = 256 edges.
// h tile stored as half2, row stride 20 words (80B): LDS.32 A-feeds conflict-free.
// Weights staged once per block in smem (conflict-free padded layout).
template <bool ENC>
__global__ void __launch_bounds__(128, 5) k_edge(const int* __restrict__ src,
                                                 const int* __restrict__ dst,
                                                 const float* __restrict__ w2,
                                                 const float* __restrict__ b2,
                                                 const float* __restrict__ w3,
                                                 const float* __restrict__ b3,
                                                 float* __restrict__ agg) {
    constexpr int OUT = ENC ? 2 : 4;
    constexpr int RW = 20;                   // u32 words per row (80B)
    __shared__ unsigned sHh[4][64 * RW];     // fp16-hi h tiles, 20KB
    __shared__ __align__(16) float sW2p[32 * 36];  // padded W2 (conflict-free frag build)
    __shared__ float sB2f[32];

    int t = threadIdx.x;
#pragma unroll
    for (int r = 0; r < 8; r++) {
        int idx = r * 128 + t;               // 1024 W2 entries
        sW2p[(idx >> 5) * 36 + (idx & 31)] = w2[idx];
    }
    if (t < 32) sB2f[t] = b2[t];
    __syncthreads();

    int warp = t >> 5, lane = t & 31;
    int base = blockIdx.x * 256 + warp * 64;
    unsigned* hb = sHh[warp];

    // ---- Phase 1: cooperative gather + stage h (fp16 hi, relu fused) ----
    {
        int q = lane >> 3, c = lane & 7;
#pragma unroll 8
        for (int g = 0; g < 16; g++) {
            int row = g * 4 + q;
            int e   = base + row;
            int sn  = src[e];
            int dn  = dst[e];
            float4 uu = g_u[dn * 8 + c];
            float4 vv = g_v[sn * 8 + c];
            unsigned a = pkrelu(uu.x + vv.x, uu.y + vv.y);
            unsigned b = pkrelu(uu.z + vv.z, uu.w + vv.w);
            *reinterpret_cast<uint2*>(hb + row * RW + 2 * c) = make_uint2(a, b);
        }
    }
    __syncwarp();

    int gg = lane >> 2, tt = lane & 3;

    // ---- B2 fragments (register-resident, hi/lo) from smem ----
    unsigned B2h[2][4][2], B2l[2][4][2];
#pragma unroll
    for (int kt = 0; kt < 2; kt++) {
#pragma unroll
        for (int nt = 0; nt < 4; nt++) {
            int k = kt * 16 + 2 * tt, n = nt * 8 + gg;
            splith2(sW2p[k * 36 + n],       sW2p[(k + 1) * 36 + n], B2h[kt][nt][0], B2l[kt][nt][0]);
            splith2(sW2p[(k + 8) * 36 + n], sW2p[(k + 9) * 36 + n], B2h[kt][nt][1], B2l[kt][nt][1]);
        }
    }

    // ---- B3 fragments (W3[32xOUT] zero-padded to n=8), hi/lo ----
    unsigned B3h[2][2], B3l[2][2];
#pragma unroll
    for (int p = 0; p < 2; p++) {
        int j0 = p * 16 + 2 * tt;
        float wa = (gg < OUT) ? w3[j0 * OUT + gg]       : 0.0f;
        float wb = (gg < OUT) ? w3[(j0 + 1) * OUT + gg] : 0.0f;
        float wc = (gg < OUT) ? w3[(j0 + 8) * OUT + gg] : 0.0f;
        float wd = (gg < OUT) ? w3[(j0 + 9) * OUT + gg] : 0.0f;
        splith2(wa, wb, B3h[p][0], B3l[p][0]);
        splith2(wc, wd, B3h[p][1], B3l[p][1]);
    }
    float b3c0 = (2 * tt < OUT)     ? b3[2 * tt]     : 0.0f;
    float b3c1 = (2 * tt + 1 < OUT) ? b3[2 * tt + 1] : 0.0f;

    float2 b2p[4];
#pragma unroll
    for (int nt = 0; nt < 4; nt++)
        b2p[nt] = *reinterpret_cast<const float2*>(&sB2f[nt * 8 + 2 * tt]);

    // ---- Phase 2: per-mt GEMM chain + immediate scatter ----
#pragma unroll
    for (int mt = 0; mt < 4; mt++) {
        int r0 = mt * 16 + gg;

        float acc[4][4];
#pragma unroll
        for (int nt = 0; nt < 4; nt++) {
            acc[nt][0] = b2p[nt].x; acc[nt][1] = b2p[nt].y;
            acc[nt][2] = b2p[nt].x; acc[nt][3] = b2p[nt].y;
        }

#pragma unroll
        for (int kt = 0; kt < 2; kt++) {
            int wbase = r0 * RW + kt * 8 + tt;
            unsigned Ah0 = hb[wbase];              // (r0,   cols k,k+1)
            unsigned Ah1 = hb[wbase + 8 * RW];     // (r0+8, cols k,k+1)
            unsigned Ah2 = hb[wbase + 4];          // (r0,   cols k+8,k+9)
            unsigned Ah3 = hb[wbase + 8 * RW + 4]; // (r0+8, cols k+8,k+9)
#pragma unroll
            for (int nt = 0; nt < 4; nt++) {
                mma16816(acc[nt][0], acc[nt][1], acc[nt][2], acc[nt][3],
                         Ah0, Ah1, Ah2, Ah3, B2h[kt][nt][0], B2h[kt][nt][1]);
                mma16816(acc[nt][0], acc[nt][1], acc[nt][2], acc[nt][3],
                         Ah0, Ah1, Ah2, Ah3, B2l[kt][nt][0], B2l[kt][nt][1]);
            }
        }

        // ---- layer 3: relu(C2) -> fp16-hi A fragments -> second MMA chain ----
        float o0 = b3c0, o1 = b3c1, o2 = b3c0, o3 = b3c1;
#pragma unroll
        for (int p = 0; p < 2; p++) {
            unsigned Ah[4];
            Ah[0] = pkrelu(acc[2 * p][0],     acc[2 * p][1]);
            Ah[1] = pkrelu(acc[2 * p][2],     acc[2 * p][3]);
            Ah[2] = pkrelu(acc[2 * p + 1][0], acc[2 * p + 1][1]);
            Ah[3] = pkrelu(acc[2 * p + 1][2], acc[2 * p + 1][3]);
            mma16816(o0, o1, o2, o3, Ah[0], Ah[1], Ah[2], Ah[3], B3h[p][0], B3h[p][1]);
            mma16816(o0, o1, o2, o3, Ah[0], Ah[1], Ah[2], Ah[3], B3l[p][0], B3l[p][1]);
        }

        // ---- scatter: C3 rows r0, r0+8; cols 2tt, 2tt+1 ----
        if (ENC) {
            if (tt == 0) {
                int d0 = dst[base + r0];
                atomicAdd(&g_agg1[d0 * 2 + 0], frelu(o0));
                atomicAdd(&g_agg1[d0 * 2 + 1], frelu(o1));
                atomicAdd(&g_cnt[d0], 1.0f);
                int d1 = dst[base + r0 + 8];
                atomicAdd(&g_agg1[d1 * 2 + 0], frelu(o2));
                atomicAdd(&g_agg1[d1 * 2 + 1], frelu(o3));
                atomicAdd(&g_cnt[d1], 1.0f);
            }
        } else {
            if (tt < 2) {
                int d0 = dst[base + r0];
                atomicAdd(&agg[d0 * 4 + 2 * tt + 0], o0);
                atomicAdd(&agg[d0 * 4 + 2 * tt + 1], o1);
                int d1 = dst[base + r0 + 8];
                atomicAdd(&agg[d1 * 4 + 2 * tt + 0], o2);
                atomicAdd(&agg[d1 * 4 + 2 * tt + 1], o3);
            }
        }
    }
}

// ---- finalize encoder (mean) + decoder layer-1 hoist into g_u/g_v ----
__global__ void k_fin1(const float* __restrict__ dw1, const float* __restrict__ db1) {
    __shared__ float sWd[2][32], sWs[2][32], sB[32];
    int t = threadIdx.x;
    if (t < 64) {
        int c = t >> 5, j = t & 31;
        float a = dw1[c * 32 + j], b = dw1[(c + 2) * 32 + j];
        sWd[c][j] = a - b;
        sWs[c][j] = b;
    }
    if (t < 32) sB[t] = db1[t];
    __syncthreads();
    int i = blockIdx.x * blockDim.x + t;
    if (i >= NN) return;
    float inv = 1.0f / fmaxf(g_cnt[i], 1.0f);
    float h0 = g_agg1[i * 2 + 0] * inv;
    float h1 = g_agg1[i * 2 + 1] * inv;
    float u[32], v[32];
#pragma unroll
    for (int j = 0; j < 32; j++) {
        u[j] = sB[j] + h0 * sWd[0][j] + h1 * sWd[1][j];
        v[j] = h0 * sWs[0][j] + h1 * sWs[1][j];
    }
#pragma unroll
    for (int j4 = 0; j4 < 8; j4++) {
        g_u[i * 8 + j4] = make_float4(u[4 * j4], u[4 * j4 + 1], u[4 * j4 + 2], u[4 * j4 + 3]);
        g_v[i * 8 + j4] = make_float4(v[4 * j4], v[4 * j4 + 1], v[4 * j4 + 2], v[4 * j4 + 3]);
    }
}

// ---- finalize output: divide by counts ----
__global__ void k_fin2(float* __restrict__ out) {
    int i = blockIdx.x * blockDim.x + threadIdx.x;
    if (i >= NN) return;
    float inv = 1.0f / fmaxf(g_cnt[i], 1.0f);
    float4 v = ((float4*)out)[i];
    v.x *= inv; v.y *= inv; v.z *= inv; v.w *= inv;
    ((float4*)out)[i] = v;
}

extern "C" void kernel_launch(void* const* d_in, const int* in_sizes, int n_in,
                              void* d_out, int out_size) {
    const float* x    = (const float*)d_in[0];
    const int*   ei   = (const int*)d_in[1];
    const float* bnw  = (const float*)d_in[2];
    const float* bnb  = (const float*)d_in[3];
    const float* ew1  = (const float*)d_in[4];
    const float* eb1  = (const float*)d_in[5];
    const float* ew2  = (const float*)d_in[6];
    const float* eb2  = (const float*)d_in[7];
    const float* ew3  = (const float*)d_in[8];
    const float* eb3  = (const float*)d_in[9];
    const float* dw1  = (const float*)d_in[10];
    const float* db1  = (const float*)d_in[11];
    const float* dw2  = (const float*)d_in[12];
    const float* db2  = (const float*)d_in[13];
    const float* dw3  = (const float*)d_in[14];
    const float* db3  = (const float*)d_in[15];
    float* out = (float*)d_out;

    const int* src = ei;
    const int* dst = ei + NE;

    const int zero_total = 8 + NN + NN * 2 + NN * 4;
    k_zero<<<(zero_total + 255) / 256, 256>>>(out);
    k_stats<<<400, 256>>>((const float4*)x);
    k_pre_enc<<<(NN + 255) / 256, 256>>>((const float4*)x, ew1, eb1, bnw, bnb);
    k_edge<true><<<NE / 256, 128>>>(src, dst, ew2, eb2, ew3, eb3, nullptr);
    k_fin1<<<(NN + 255) / 256, 256>>>(dw1, db1);
    k_edge<false><<<NE / 256, 128>>>(src, dst, dw2, db2, dw3, db3, out);
    k_fin2<<<(NN + 255) / 256, 256>>>(out);
}

// round 17
// speedup vs baseline: 1.8467x; 1.2187x over previous
#include <cuda_runtime.h>
#include <cuda_fp16.h>

#define NN 100000
#define NE 3200000

// ---- scratch (device globals; no allocation allowed) ----
__device__ __align__(128) uint4 g_uh[NN * 4];   // per-node dst-side layer-1 partial (+b1), fp16x2, 64B/node
__device__ __align__(128) uint4 g_vh[NN * 4];   // per-node src-side layer-1 partial, fp16x2, 64B/node
__device__ float  g_agg1[NN * 2];   // encoder aggregation (HID=2)
__device__ float  g_cnt[NN];        // in-degree counts
__device__ float  g_stats[8];       // BN: col sums [0..3], col sumsq [4..7]

__device__ __forceinline__ float frelu(float x) { return fmaxf(x, 0.0f); }

// fp16 hi/lo split helpers (Markidis-style fp32 emulation on HMMA)
__device__ __forceinline__ void splith2(float x, float y, unsigned& hi, unsigned& lo) {
    __half2 h = __floats2half2_rn(x, y);
    float2 fb = __half22float2(h);
    __half2 l = __floats2half2_rn(x - fb.x, y - fb.y);
    hi = *reinterpret_cast<unsigned*>(&h);
    lo = *reinterpret_cast<unsigned*>(&l);
}

__device__ __forceinline__ unsigned h2u(__half2 h) {
    return *reinterpret_cast<unsigned*>(&h);
}
__device__ __forceinline__ __half2 u2h(unsigned u) {
    return *reinterpret_cast<__half2*>(&u);
}
__device__ __forceinline__ unsigned pkh2(float x, float y) {
    return h2u(__floats2half2_rn(x, y));
}

// pack two fp32 to fp16x2 with relu applied post-round (== pre-round relu)
__device__ __forceinline__ unsigned pkrelu(float x, float y) {
    __half2 z = __float2half2_rn(0.0f);
    return h2u(__hmax2(__floats2half2_rn(x, y), z));
}

// fp16x2 add + relu (for u+v from fp16 tables)
__device__ __forceinline__ unsigned addrelu(unsigned a, unsigned b) {
    __half2 z = __float2half2_rn(0.0f);
    return h2u(__hmax2(__hadd2(u2h(a), u2h(b)), z));
}

__device__ __forceinline__ void mma16816(float& c0, float& c1, float& c2, float& c3,
                                         unsigned a0, unsigned a1, unsigned a2, unsigned a3,
                                         unsigned b0, unsigned b1) {
    asm volatile(
        "mma.sync.aligned.m16n8k16.row.col.f32.f16.f16.f32 "
        "{%0,%1,%2,%3}, {%4,%5,%6,%7}, {%8,%9}, {%0,%1,%2,%3};\n"
        : "+f"(c0), "+f"(c1), "+f"(c2), "+f"(c3)
        : "r"(a0), "r"(a1), "r"(a2), "r"(a3), "r"(b0), "r"(b1));
}

// ---- zero the per-replay accumulators ----
__global__ void k_zero(float* __restrict__ out) {
    int i = blockIdx.x * blockDim.x + threadIdx.x;
    const int total = 8 + NN + NN * 2 + NN * 4;
    if (i >= total) return;
    if (i < 8)               g_stats[i] = 0.0f;
    else if (i < 8 + NN)     g_cnt[i - 8] = 0.0f;
    else if (i < 8 + 3 * NN) g_agg1[i - 8 - NN] = 0.0f;
    else                     out[i - 8 - 3 * NN] = 0.0f;
}

// ---- BatchNorm statistics ----
__global__ void k_stats(const float4* __restrict__ x) {
    float s[8] = {0, 0, 0, 0, 0, 0, 0, 0};
    for (int i = blockIdx.x * blockDim.x + threadIdx.x; i < NN;
         i += gridDim.x * blockDim.x) {
        float4 v = x[i];
        s[0] += v.x; s[1] += v.y; s[2] += v.z; s[3] += v.w;
        s[4] += v.x * v.x; s[5] += v.y * v.y; s[6] += v.z * v.z; s[7] += v.w * v.w;
    }
#pragma unroll
    for (int k = 0; k < 8; k++) {
#pragma unroll
        for (int o = 16; o > 0; o >>= 1)
            s[k] += __shfl_down_sync(0xffffffffu, s[k], o);
    }
    __shared__ float sh[8][8];
    int w = threadIdx.x >> 5, l = threadIdx.x & 31;
    if (l == 0) {
#pragma unroll
        for (int k = 0; k < 8; k++) sh[w][k] = s[k];
    }
    __syncthreads();
    if (threadIdx.x < 8) {
        float t = 0.0f;
#pragma unroll
        for (int ww = 0; ww < 8; ww++) t += sh[ww][threadIdx.x];
        atomicAdd(&g_stats[threadIdx.x], t);
    }
}

// ---- per-node: BN normalize + encoder layer-1 hoist (fp16 pack) ----
__global__ void k_pre_enc(const float4* __restrict__ x,
                          const float* __restrict__ w1, const float* __restrict__ b1,
                          const float* __restrict__ bnw, const float* __restrict__ bnb) {
    __shared__ float sWd[4][32], sWs[4][32], sB[32];
    __shared__ float sm[4], sinv[4], sbw[4], sbb[4];
    int t = threadIdx.x;
    if (t < 128) {
        int c = t >> 5, j = t & 31;
        float a = w1[c * 32 + j], b = w1[(c + 4) * 32 + j];
        sWd[c][j] = a - b;
        sWs[c][j] = b;
    }
    if (t < 32) sB[t] = b1[t];
    if (t < 4) {
        float mean = g_stats[t] * (1.0f / NN);
        float var  = g_stats[4 + t] * (1.0f / NN) - mean * mean;
        sm[t] = mean;
        sinv[t] = rsqrtf(var + 1e-5f);
        sbw[t] = bnw[t];
        sbb[t] = bnb[t];
    }
    __syncthreads();
    int i = blockIdx.x * blockDim.x + t;
    if (i >= NN) return;
    float4 xv = x[i];
    float xh[4];
    xh[0] = (xv.x - sm[0]) * sinv[0] * sbw[0] + sbb[0];
    xh[1] = (xv.y - sm[1]) * sinv[1] * sbw[1] + sbb[1];
    xh[2] = (xv.z - sm[2]) * sinv[2] * sbw[2] + sbb[2];
    xh[3] = (xv.w - sm[3]) * sinv[3] * sbw[3] + sbb[3];
    float u[32], v[32];
#pragma unroll
    for (int j = 0; j < 32; j++) {
        float uu = sB[j], vv = 0.0f;
#pragma unroll
        for (int c = 0; c < 4; c++) {
            uu += xh[c] * sWd[c][j];
            vv += xh[c] * sWs[c][j];
        }
        u[j] = uu; v[j] = vv;
    }
#pragma unroll
    for (int w = 0; w < 4; w++) {
        g_uh[i * 4 + w] = make_uint4(pkh2(u[8 * w + 0], u[8 * w + 1]),
                                     pkh2(u[8 * w + 2], u[8 * w + 3]),
                                     pkh2(u[8 * w + 4], u[8 * w + 5]),
                                     pkh2(u[8 * w + 6], u[8 * w + 7]));
        g_vh[i * 4 + w] = make_uint4(pkh2(v[8 * w + 0], v[8 * w + 1]),
                                     pkh2(v[8 * w + 2], v[8 * w + 3]),
                                     pkh2(v[8 * w + 4], v[8 * w + 5]),
                                     pkh2(v[8 * w + 6], v[8 * w + 7]));
    }
}

// ---- per-edge MLP: tensor cores; A-side fp16-hi, B2 hi+lo (2-pass) ----
// Block = 128 threads = 4 warps; warp owns a 64-edge tile; block = 256 edges.
// u/v tables fp16 (64B rows): 4 lanes/row gather, 8 rows per instruction.
// h tile half2, row stride 20 words (80B): LDS.32 A-feeds conflict-free.
template <bool ENC>
__global__ void __launch_bounds__(128, 5) k_edge(const int* __restrict__ src,
                                                 const int* __restrict__ dst,
                                                 const float* __restrict__ w2,
                                                 const float* __restrict__ b2,
                                                 const float* __restrict__ w3,
                                                 const float* __restrict__ b3,
                                                 float* __restrict__ agg) {
    constexpr int OUT = ENC ? 2 : 4;
    constexpr int RW = 20;                   // u32 words per row (80B)
    __shared__ unsigned sHh[4][64 * RW];     // fp16-hi h tiles, 20KB
    __shared__ __align__(16) float sW2p[32 * 36];  // padded W2 (conflict-free frag build)
    __shared__ float sB2f[32];

    int t = threadIdx.x;
#pragma unroll
    for (int r = 0; r < 8; r++) {
        int idx = r * 128 + t;               // 1024 W2 entries
        sW2p[(idx >> 5) * 36 + (idx & 31)] = w2[idx];
    }
    if (t < 32) sB2f[t] = b2[t];
    __syncthreads();

    int warp = t >> 5, lane = t & 31;
    int base = blockIdx.x * 256 + warp * 64;
    unsigned* hb = sHh[warp];

    // ---- Phase 1: cooperative gather (fp16 tables) + stage h ----
    {
        int q = lane >> 2, c = lane & 3;     // 8 rows / instruction, 4 x 16B segments
#pragma unroll
        for (int g = 0; g < 8; g++) {
            int row = g * 8 + q;
            int e   = base + row;
            int sn  = src[e];
            int dn  = dst[e];
            uint4 uu = g_uh[dn * 4 + c];
            uint4 vv = g_vh[sn * 4 + c];
            uint4 h;
            h.x = addrelu(uu.x, vv.x);
            h.y = addrelu(uu.y, vv.y);
            h.z = addrelu(uu.z, vv.z);
            h.w = addrelu(uu.w, vv.w);
            *reinterpret_cast<uint4*>(hb + row * RW + 4 * c) = h;
        }
    }
    __syncwarp();

    int gg = lane >> 2, tt = lane & 3;

    // ---- B2 fragments (register-resident, hi/lo) from smem ----
    unsigned B2h[2][4][2], B2l[2][4][2];
#pragma unroll
    for (int kt = 0; kt < 2; kt++) {
#pragma unroll
        for (int nt = 0; nt < 4; nt++) {
            int k = kt * 16 + 2 * tt, n = nt * 8 + gg;
            splith2(sW2p[k * 36 + n],       sW2p[(k + 1) * 36 + n], B2h[kt][nt][0], B2l[kt][nt][0]);
            splith2(sW2p[(k + 8) * 36 + n], sW2p[(k + 9) * 36 + n], B2h[kt][nt][1], B2l[kt][nt][1]);
        }
    }

    // ---- B3 fragments (W3[32xOUT] zero-padded to n=8), hi/lo ----
    unsigned B3h[2][2], B3l[2][2];
#pragma unroll
    for (int p = 0; p < 2; p++) {
        int j0 = p * 16 + 2 * tt;
        float wa = (gg < OUT) ? w3[j0 * OUT + gg]       : 0.0f;
        float wb = (gg < OUT) ? w3[(j0 + 1) * OUT + gg] : 0.0f;
        float wc = (gg < OUT) ? w3[(j0 + 8) * OUT + gg] : 0.0f;
        float wd = (gg < OUT) ? w3[(j0 + 9) * OUT + gg] : 0.0f;
        splith2(wa, wb, B3h[p][0], B3l[p][0]);
        splith2(wc, wd, B3h[p][1], B3l[p][1]);
    }
    float b3c0 = (2 * tt < OUT)     ? b3[2 * tt]     : 0.0f;
    float b3c1 = (2 * tt + 1 < OUT) ? b3[2 * tt + 1] : 0.0f;

    float2 b2p[4];
#pragma unroll
    for (int nt = 0; nt < 4; nt++)
        b2p[nt] = *reinterpret_cast<const float2*>(&sB2f[nt * 8 + 2 * tt]);

    // ---- Phase 2: per-mt GEMM chain + immediate scatter ----
#pragma unroll
    for (int mt = 0; mt < 4; mt++) {
        int r0 = mt * 16 + gg;

        float acc[4][4];
#pragma unroll
        for (int nt = 0; nt < 4; nt++) {
            acc[nt][0] = b2p[nt].x; acc[nt][1] = b2p[nt].y;
            acc[nt][2] = b2p[nt].x; acc[nt][3] = b2p[nt].y;
        }

#pragma unroll
        for (int kt = 0; kt < 2; kt++) {
            int wbase = r0 * RW + kt * 8 + tt;
            unsigned Ah0 = hb[wbase];              // (r0,   cols k,k+1)
            unsigned Ah1 = hb[wbase + 8 * RW];     // (r0+8, cols k,k+1)
            unsigned Ah2 = hb[wbase + 4];          // (r0,   cols k+8,k+9)
            unsigned Ah3 = hb[wbase + 8 * RW + 4]; // (r0+8, cols k+8,k+9)
#pragma unroll
            for (int nt = 0; nt < 4; nt++) {
                mma16816(acc[nt][0], acc[nt][1], acc[nt][2], acc[nt][3],
                         Ah0, Ah1, Ah2, Ah3, B2h[kt][nt][0], B2h[kt][nt][1]);
                mma16816(acc[nt][0], acc[nt][1], acc[nt][2], acc[nt][3],
                         Ah0, Ah1, Ah2, Ah3, B2l[kt][nt][0], B2l[kt][nt][1]);
            }
        }

        // ---- layer 3: relu(C2) -> fp16-hi A fragments -> second MMA chain ----
        float o0 = b3c0, o1 = b3c1, o2 = b3c0, o3 = b3c1;
#pragma unroll
        for (int p = 0; p < 2; p++) {
            unsigned Ah[4];
            Ah[0] = pkrelu(acc[2 * p][0],     acc[2 * p][1]);
            Ah[1] = pkrelu(acc[2 * p][2],     acc[2 * p][3]);
            Ah[2] = pkrelu(acc[2 * p + 1][0], acc[2 * p + 1][1]);
            Ah[3] = pkrelu(acc[2 * p + 1][2], acc[2 * p + 1][3]);
            mma16816(o0, o1, o2, o3, Ah[0], Ah[1], Ah[2], Ah[3], B3h[p][0], B3h[p][1]);
            mma16816(o0, o1, o2, o3, Ah[0], Ah[1], Ah[2], Ah[3], B3l[p][0], B3l[p][1]);
        }

        // ---- scatter: C3 rows r0, r0+8; cols 2tt, 2tt+1 ----
        if (ENC) {
            if (tt == 0) {
                int d0 = dst[base + r0];
                atomicAdd(&g_agg1[d0 * 2 + 0], frelu(o0));
                atomicAdd(&g_agg1[d0 * 2 + 1], frelu(o1));
                atomicAdd(&g_cnt[d0], 1.0f);
                int d1 = dst[base + r0 + 8];
                atomicAdd(&g_agg1[d1 * 2 + 0], frelu(o2));
                atomicAdd(&g_agg1[d1 * 2 + 1], frelu(o3));
                atomicAdd(&g_cnt[d1], 1.0f);
            }
        } else {
            if (tt < 2) {
                int d0 = dst[base + r0];
                atomicAdd(&agg[d0 * 4 + 2 * tt + 0], o0);
                atomicAdd(&agg[d0 * 4 + 2 * tt + 1], o1);
                int d1 = dst[base + r0 + 8];
                atomicAdd(&agg[d1 * 4 + 2 * tt + 0], o2);
                atomicAdd(&agg[d1 * 4 + 2 * tt + 1], o3);
            }
        }
    }
}

// ---- finalize encoder (mean) + decoder layer-1 hoist into g_uh/g_vh ----
__global__ void k_fin1(const float* __restrict__ dw1, const float* __restrict__ db1) {
    __shared__ float sWd[2][32], sWs[2][32], sB[32];
    int t = threadIdx.x;
    if (t < 64) {
        int c = t >> 5, j = t & 31;
        float a = dw1[c * 32 + j], b = dw1[(c + 2) * 32 + j];
        sWd[c][j] = a - b;
        sWs[c][j] = b;
    }
    if (t < 32) sB[t] = db1[t];
    __syncthreads();
    int i = blockIdx.x * blockDim.x + t;
    if (i >= NN) return;
    float inv = 1.0f / fmaxf(g_cnt[i], 1.0f);
    float h0 = g_agg1[i * 2 + 0] * inv;
    float h1 = g_agg1[i * 2 + 1] * inv;
    float u[32], v[32];
#pragma unroll
    for (int j = 0; j < 32; j++) {
        u[j] = sB[j] + h0 * sWd[0][j] + h1 * sWd[1][j];
        v[j] = h0 * sWs[0][j] + h1 * sWs[1][j];
    }
#pragma unroll
    for (int w = 0; w < 4; w++) {
        g_uh[i * 4 + w] = make_uint4(pkh2(u[8 * w + 0], u[8 * w + 1]),
                                     pkh2(u[8 * w + 2], u[8 * w + 3]),
                                     pkh2(u[8 * w + 4], u[8 * w + 5]),
                                     pkh2(u[8 * w + 6], u[8 * w + 7]));
        g_vh[i * 4 + w] = make_uint4(pkh2(v[8 * w + 0], v[8 * w + 1]),
                                     pkh2(v[8 * w + 2], v[8 * w + 3]),
                                     pkh2(v[8 * w + 4], v[8 * w + 5]),
                                     pkh2(v[8 * w + 6], v[8 * w + 7]));
    }
}

// ---- finalize output: divide by counts ----
__global__ void k_fin2(float* __restrict__ out) {
    int i = blockIdx.x * blockDim.x + threadIdx.x;
    if (i >= NN) return;
    float inv = 1.0f / fmaxf(g_cnt[i], 1.0f);
    float4 v = ((float4*)out)[i];
    v.x *= inv; v.y *= inv; v.z *= inv; v.w *= inv;
    ((float4*)out)[i] = v;
}

extern "C" void kernel_launch(void* const* d_in, const int* in_sizes, int n_in,
                              void* d_out, int out_size) {
    const float* x    = (const float*)d_in[0];
    const int*   ei   = (const int*)d_in[1];
    const float* bnw  = (const float*)d_in[2];
    const float* bnb  = (const float*)d_in[3];
    const float* ew1  = (const float*)d_in[4];
    const float* eb1  = (const float*)d_in[5];
    const float* ew2  = (const float*)d_in[6];
    const float* eb2  = (const float*)d_in[7];
    const float* ew3  = (const float*)d_in[8];
    const float* eb3  = (const float*)d_in[9];
    const float* dw1  = (const float*)d_in[10];
    const float* db1  = (const float*)d_in[11];
    const float* dw2  = (const float*)d_in[12];
    const float* db2  = (const float*)d_in[13];
    const float* dw3  = (const float*)d_in[14];
    const float* db3  = (const float*)d_in[15];
    float* out = (float*)d_out;

    const int* src = ei;
    const int* dst = ei + NE;

    const int zero_total = 8 + NN + NN * 2 + NN * 4;
    k_zero<<<(zero_total + 255) / 256, 256>>>(out);
    k_stats<<<400, 256>>>((const float4*)x);
    k_pre_enc<<<(NN + 255) / 256, 256>>>((const float4*)x, ew1, eb1, bnw, bnb);
    k_edge<true><<<NE / 256, 128>>>(src, dst, ew2, eb2, ew3, eb3, nullptr);
    k_fin1<<<(NN + 255) / 256, 256>>>(dw1, db1);
    k_edge<false><<<NE / 256, 128>>>(src, dst, dw2, db2, dw3, db3, out);
    k_fin2<<<(NN + 255) / 256, 256>>>(out);
}